// round 12
// baseline (speedup 1.0000x reference)
#include <cuda_runtime.h>
#include <cuda_fp16.h>
#include <cstdint>

#define DINLINE __device__ __forceinline__

static constexpr int AGENTS = 8;
static constexpr int ENVS   = 4096;
static constexpr int ODIM   = 256;
static constexpr int H1D    = 1024;
static constexpr int H2D    = 1024;
static constexpr int H3D    = 512;
static constexpr int SNETS  = 4;

// Static device scratch (no allocations allowed). fp16 fragment-major buffers.
__device__ __half g_xf [(size_t)AGENTS * ENVS * ODIM];
__device__ __half g_h1 [(size_t)AGENTS * ENVS * H1D];
__device__ __half g_h2 [(size_t)AGENTS * ENVS * H2D];
__device__ __half g_w1f[(size_t)SNETS * H1D * ODIM];
__device__ __half g_w2f[(size_t)SNETS * H2D * H1D];
__device__ __half g_w3f[(size_t)SNETS * H3D * H2D];

// ---------------- helpers ----------------
DINLINE uint32_t packh2(float lo, float hi) {
    __half2 h = __floats2half2_rn(lo, hi);
    return *(uint32_t*)&h;
}

// m16n8k16 fp16 mma, f32 accum.
DINLINE void mma_f16(float* c, const uint4& a, const uint2& b) {
    asm volatile(
        "mma.sync.aligned.m16n8k16.row.col.f32.f16.f16.f32 "
        "{%0,%1,%2,%3}, {%4,%5,%6,%7}, {%8,%9}, {%0,%1,%2,%3};"
        : "+f"(c[0]), "+f"(c[1]), "+f"(c[2]), "+f"(c[3])
        : "r"(a.x), "r"(a.y), "r"(a.z), "r"(a.w), "r"(b.x), "r"(b.y));
}

DINLINE uint32_t smem_u32(const void* p) { return (uint32_t)__cvta_generic_to_shared(p); }

DINLINE void cp16(uint32_t s, const void* g) {
    asm volatile("cp.async.cg.shared.global [%0], [%1], 16;" :: "r"(s), "l"(g));
}
DINLINE void cp_commit() { asm volatile("cp.async.commit_group;"); }
template <int N> DINLINE void cp_wait() { asm volatile("cp.async.wait_group %0;" :: "n"(N)); }

// seps_idx dtype sniff: int64 values 0..3 -> odd int32 words all zero.
DINLINE int load_sep(const void* p, int ag) {
    const int* a = (const int*)p;
    if ((a[1] | a[3] | a[5] | a[7]) == 0) return (int)((const long long*)p)[ag];
    return a[ag];
}

// ---------------- merged prep: x + W1/W2/W3 -> fp16 fragment layouts ----------------
// Block ranges: [0,2048) frag_x ; [2048,2560) W1 ; [2560,4608) W2 ; [4608,5632) W3.
__global__ __launch_bounds__(256)
void prep_kernel(const float* __restrict__ x,
                 const float* __restrict__ W1, const float* __restrict__ W2,
                 const float* __restrict__ W3,
                 __half* __restrict__ xf, __half* __restrict__ w1f,
                 __half* __restrict__ w2f, __half* __restrict__ w3f)
{
    __shared__ float s[16 * 256];     // 16 KB; weight path uses a [32][65] view
    const int b = blockIdx.x;
    const int tid = threadIdx.x;

    if (b < 2048) {
        // ---- x -> A-fragment (K=256): chunk = m_blk*(K/16)+kc, uint4 idx = chunk*32+lane
        const int mb = b & 255, ag = b >> 8;
        const float* xp = x + ((size_t)ag * ENVS + (size_t)mb * 16) * ODIM;
        #pragma unroll
        for (int i = 0; i < 16; ++i) s[tid + i * 256] = xp[tid + i * 256];
        __syncthreads();
        uint4* op = (uint4*)(xf + ((size_t)ag * ENVS + (size_t)mb * 16) * ODIM);
        #pragma unroll
        for (int j = 0; j < 2; ++j) {
            int t = tid + j * 256;
            int kc = t >> 5, ln = t & 31;
            int g = ln >> 2, tg = ln & 3;
            const float* r0 = s + g * 256 + kc * 16;
            const float* r1 = s + (g + 8) * 256 + kc * 16;
            uint4 q;
            q.x = packh2(r0[2 * tg],     r0[2 * tg + 1]);
            q.y = packh2(r1[2 * tg],     r1[2 * tg + 1]);
            q.z = packh2(r0[2 * tg + 8], r0[2 * tg + 9]);
            q.w = packh2(r1[2 * tg + 8], r1[2 * tg + 9]);
            op[kc * 32 + ln] = q;
        }
    } else {
        // ---- W [S][K][N] -> B-fragment: chunk = n_blk*(K/16)+kc, uint2 idx = chunk*32+lane
        const float* W; __half* out; int K, N, i;
        if (b < 2560)      { W = W1; out = w1f; K = ODIM; N = H1D; i = b - 2048; }
        else if (b < 4608) { W = W2; out = w2f; K = H1D;  N = H2D; i = b - 2560; }
        else               { W = W3; out = w3f; K = H2D;  N = H3D; i = b - 4608; }
        const int nb64 = N >> 6;
        const int n0 = (i % nb64) * 64;
        const int k0 = ((i / nb64) % (K >> 5)) * 32;
        const int net = i / (nb64 * (K >> 5));
        float (*t)[65] = (float(*)[65])s;
        const float* wp = W + (size_t)net * K * N;
        #pragma unroll
        for (int ii = 0; ii < 8; ++ii) {
            int o = tid + ii * 256;
            int k = o >> 6, n = o & 63;
            t[k][n] = wp[(size_t)(k0 + k) * N + n0 + n];
        }
        __syncthreads();
        uint2* op = (uint2*)(out + (size_t)net * N * K);
        const int KB16 = K >> 4;
        #pragma unroll
        for (int ii = 0; ii < 2; ++ii) {
            int tt = tid + ii * 256;
            int c = tt >> 5, ln = tt & 31;
            int nb = c >> 1, kc = c & 1;
            int g = ln >> 2, tg = ln & 3;
            uint2 q;
            q.x = packh2(t[kc * 16 + 2 * tg][nb * 8 + g],     t[kc * 16 + 2 * tg + 1][nb * 8 + g]);
            q.y = packh2(t[kc * 16 + 2 * tg + 8][nb * 8 + g], t[kc * 16 + 2 * tg + 9][nb * 8 + g]);
            int chunk = ((n0 >> 3) + nb) * KB16 + (k0 >> 4) + kc;
            op[chunk * 32 + ln] = q;
        }
    }
}

// ---------------- main GEMM, fp16 m16n8k16, k32 stages, 4-deep cp.async ----------------
// CTA 128 thr = 4 warps (2x2), CTA tile 128x128, warp tile 64x64.
// Stage 16 KB: A [8 m-blk][2 kc][32 ln] uint4 (8 KB) + B [16 n-blk][2 kc][16 ch] 16B (8 KB).
template <int K, int N, bool FINAL>
__global__ __launch_bounds__(128, 2)
void gemm_kernel(const __half* __restrict__ Af, const __half* __restrict__ Bf,
                 const float* __restrict__ bias, const void* __restrict__ seps,
                 void* __restrict__ OutV)
{
    constexpr int KC = K / 16;          // k16 chunks in global frag layout
    constexpr int NS = K / 32;          // k32 pipeline stages
    constexpr uint32_t STAGE_B = 16384;
    extern __shared__ __align__(16) float s_tile[];   // 4 stages = 64 KB

    const int tid = threadIdx.x, lane = tid & 31, warp = tid >> 5;
    const int wm = warp >> 1, wn = warp & 1;
    const int ag = blockIdx.z;
    const int sel = load_sep(seps, ag);
    const int mb0 = blockIdx.y * 8;
    const int nb0 = blockIdx.x * 16;

    const uint4* A4 = (const uint4*)(Af + (size_t)ag * ENVS * K);
    const uint4* B4 = (const uint4*)(Bf + (size_t)sel * N * K);

    // cp.async assignments: 4 A chunks + 4 B chunks (16B) per thread per stage.
    const uint32_t s_base = smem_u32(s_tile);
    const uint4* gA[4];
    const uint4* gB[4];
    uint32_t oA[4], oB[4];
    #pragma unroll
    for (int j = 0; j < 4; ++j) {
        int c = j * 128 + tid;                       // 0..511
        int sa = c >> 6, ra = c & 63;                // A: m-blk slice
        int kca = ra >> 5, ia = ra & 31;
        gA[j] = A4 + (size_t)(mb0 + sa) * KC * 32 + kca * 32 + ia;
        oA[j] = (uint32_t)(sa * 1024 + kca * 512 + ia * 16);
        int sb = c >> 5, rb = c & 31;                // B: n-blk slice
        int kcb = rb >> 4, ib = rb & 15;
        gB[j] = B4 + (size_t)(nb0 + sb) * KC * 16 + kcb * 16 + ib;
        oB[j] = (uint32_t)(8192 + sb * 512 + kcb * 256 + ib * 16);
    }

    auto issue_stage = [&](int s, int slot) {
        uint32_t sb = s_base + (uint32_t)slot * STAGE_B;
        #pragma unroll
        for (int j = 0; j < 4; ++j) {
            cp16(sb + oA[j], gA[j] + (size_t)s * 64);   // 2 kc per stage = 64 uint4
            cp16(sb + oB[j], gB[j] + (size_t)s * 32);
        }
    };

    float acc[4][8][4];
    #pragma unroll
    for (int mi = 0; mi < 4; ++mi)
        #pragma unroll
        for (int ni = 0; ni < 8; ++ni)
            #pragma unroll
            for (int j = 0; j < 4; ++j) acc[mi][ni][j] = 0.0f;

    issue_stage(0, 0); cp_commit();
    issue_stage(1, 1); cp_commit();
    issue_stage(2, 2); cp_commit();

    #pragma unroll 1
    for (int s = 0; s < NS; ++s) {
        cp_wait<2>();
        __syncthreads();
        {
            int nxt = s + 3;
            if (nxt < NS) issue_stage(nxt, nxt & 3);
            cp_commit();
        }
        const int slot = s & 3;
        const uint4* a_s = (const uint4*)(s_tile + slot * 4096);
        const uint2* b_s = (const uint2*)(s_tile + slot * 4096 + 2048);
        #pragma unroll
        for (int kcl = 0; kcl < 2; ++kcl) {
            uint4 a[4];
            uint2 b[8];
            #pragma unroll
            for (int mi = 0; mi < 4; ++mi) a[mi] = a_s[(wm * 4 + mi) * 64 + kcl * 32 + lane];
            #pragma unroll
            for (int ni = 0; ni < 8; ++ni) b[ni] = b_s[(wn * 8 + ni) * 64 + kcl * 32 + lane];
            #pragma unroll
            for (int mi = 0; mi < 4; ++mi)
                #pragma unroll
                for (int ni = 0; ni < 8; ++ni)
                    mma_f16(acc[mi][ni], a[mi], b[ni]);
        }
    }

    // ---------------- epilogue ----------------
    const float* bp = bias + (size_t)sel * N;
    const int g = lane >> 2, tg = lane & 3;
    const int m_blk0 = mb0 + wm * 4;
    const int n_blk0 = nb0 + wn * 8;

    if (FINAL) {
        float* ob = (float*)OutV + (size_t)ag * ENVS * N;
        #pragma unroll
        for (int mi = 0; mi < 4; ++mi) {
            const int row0 = (m_blk0 + mi) * 16 + g;
            #pragma unroll
            for (int ni = 0; ni < 8; ++ni) {
                const int nb = (n_blk0 + ni) * 8 + 2 * tg;
                const float2 bb = *(const float2*)(bp + nb);
                *(float2*)(ob + (size_t)row0 * N + nb) =
                    make_float2(acc[mi][ni][0] + bb.x, acc[mi][ni][1] + bb.y);
                *(float2*)(ob + (size_t)(row0 + 8) * N + nb) =
                    make_float2(acc[mi][ni][2] + bb.x, acc[mi][ni][3] + bb.y);
            }
        }
    } else {
        // bias + relu + fp16 round; C-frag pairs pack directly into next layer's A-frag.
        uint4* ob4 = (uint4*)((__half*)OutV + (size_t)ag * ENVS * N);
        constexpr int KCn = N / 16;
        #pragma unroll
        for (int mi = 0; mi < 4; ++mi) {
            #pragma unroll
            for (int j = 0; j < 4; ++j) {
                uint32_t h[2][2];
                #pragma unroll
                for (int e = 0; e < 2; ++e) {
                    const int ni = 2 * j + e;
                    const int nb = (n_blk0 + ni) * 8 + 2 * tg;
                    const float2 bb = *(const float2*)(bp + nb);
                    float c0 = fmaxf(acc[mi][ni][0] + bb.x, 0.0f);
                    float c1 = fmaxf(acc[mi][ni][1] + bb.y, 0.0f);
                    float c2 = fmaxf(acc[mi][ni][2] + bb.x, 0.0f);
                    float c3 = fmaxf(acc[mi][ni][3] + bb.y, 0.0f);
                    h[e][0] = packh2(c0, c1);
                    h[e][1] = packh2(c2, c3);
                }
                uint4 q;
                q.x = h[0][0]; q.y = h[0][1]; q.z = h[1][0]; q.w = h[1][1];
                const int chunk = (m_blk0 + mi) * KCn + (n_blk0 >> 1) + j;
                ob4[chunk * 32 + lane] = q;
            }
        }
    }
}

// ---------------- host ----------------
extern "C" void kernel_launch(void* const* d_in, const int* in_sizes, int n_in,
                              void* d_out, int out_size) {
    (void)in_sizes; (void)n_in; (void)out_size;
    const float* x  = (const float*)d_in[0];
    const float* W1 = (const float*)d_in[1];
    const float* b1 = (const float*)d_in[2];
    const float* W2 = (const float*)d_in[3];
    const float* b2 = (const float*)d_in[4];
    const float* W3 = (const float*)d_in[5];
    const float* b3 = (const float*)d_in[6];
    const void*  sp = d_in[7];

    __half *xf, *h1, *h2, *w1f, *w2f, *w3f;
    cudaGetSymbolAddress((void**)&xf,  g_xf);
    cudaGetSymbolAddress((void**)&h1,  g_h1);
    cudaGetSymbolAddress((void**)&h2,  g_h2);
    cudaGetSymbolAddress((void**)&w1f, g_w1f);
    cudaGetSymbolAddress((void**)&w2f, g_w2f);
    cudaGetSymbolAddress((void**)&w3f, g_w3f);

    constexpr int SMEM = 4 * 16384;   // 64 KB dynamic smem, 4 pipeline stages
    cudaFuncSetAttribute(gemm_kernel<ODIM, H1D, false>, cudaFuncAttributeMaxDynamicSharedMemorySize, SMEM);
    cudaFuncSetAttribute(gemm_kernel<H1D,  H2D, false>, cudaFuncAttributeMaxDynamicSharedMemorySize, SMEM);
    cudaFuncSetAttribute(gemm_kernel<H2D,  H3D, true >, cudaFuncAttributeMaxDynamicSharedMemorySize, SMEM);

    prep_kernel<<<5632, 256>>>(x, W1, W2, W3, xf, w1f, w2f, w3f);
    gemm_kernel<ODIM, H1D, false><<<dim3(H1D / 128, ENVS / 128, AGENTS), 128, SMEM>>>(xf, w1f, b1, sp, h1);
    gemm_kernel<H1D,  H2D, false><<<dim3(H2D / 128, ENVS / 128, AGENTS), 128, SMEM>>>(h1, w2f, b2, sp, h2);
    gemm_kernel<H2D,  H3D, true ><<<dim3(H3D / 128, ENVS / 128, AGENTS), 128, SMEM>>>(h2, w3f, b3, sp, d_out);
}

// round 14
// speedup vs baseline: 1.0496x; 1.0496x over previous
#include <cuda_runtime.h>
#include <cuda_fp16.h>
#include <cstdint>

#define DINLINE __device__ __forceinline__

static constexpr int AGENTS = 8;
static constexpr int ENVS   = 4096;
static constexpr int ODIM   = 256;
static constexpr int H1D    = 1024;
static constexpr int H2D    = 1024;
static constexpr int H3D    = 512;
static constexpr int SNETS  = 4;

// Static device scratch (no allocations allowed). fp16 fragment-major buffers.
__device__ __half g_xf [(size_t)AGENTS * ENVS * ODIM];
__device__ __half g_h1 [(size_t)AGENTS * ENVS * H1D];
__device__ __half g_h2 [(size_t)AGENTS * ENVS * H2D];
__device__ __half g_w1f[(size_t)SNETS * H1D * ODIM];
__device__ __half g_w2f[(size_t)SNETS * H2D * H1D];
__device__ __half g_w3f[(size_t)SNETS * H3D * H2D];

// ---------------- helpers ----------------
DINLINE uint32_t packh2(float lo, float hi) {
    __half2 h = __floats2half2_rn(lo, hi);
    return *(uint32_t*)&h;
}

// m16n8k16 fp16 mma, f32 accum.
DINLINE void mma_f16(float* c, const uint4& a, const uint2& b) {
    asm volatile(
        "mma.sync.aligned.m16n8k16.row.col.f32.f16.f16.f32 "
        "{%0,%1,%2,%3}, {%4,%5,%6,%7}, {%8,%9}, {%0,%1,%2,%3};"
        : "+f"(c[0]), "+f"(c[1]), "+f"(c[2]), "+f"(c[3])
        : "r"(a.x), "r"(a.y), "r"(a.z), "r"(a.w), "r"(b.x), "r"(b.y));
}

DINLINE uint32_t smem_u32(const void* p) { return (uint32_t)__cvta_generic_to_shared(p); }

DINLINE void cp16(uint32_t s, const void* g) {
    asm volatile("cp.async.cg.shared.global [%0], [%1], 16;" :: "r"(s), "l"(g));
}
DINLINE void cp_commit() { asm volatile("cp.async.commit_group;"); }
template <int N> DINLINE void cp_wait() { asm volatile("cp.async.wait_group %0;" :: "n"(N)); }

// seps_idx dtype sniff: int64 values 0..3 -> odd int32 words all zero.
DINLINE int load_sep(const void* p, int ag) {
    const int* a = (const int*)p;
    if ((a[1] | a[3] | a[5] | a[7]) == 0) return (int)((const long long*)p)[ag];
    return a[ag];
}

// ---------------- merged prep: x + W1/W2/W3 -> fp16 fragment layouts ----------------
// Block ranges: [0,2048) frag_x ; [2048,2560) W1 ; [2560,4608) W2 ; [4608,5632) W3.
__global__ __launch_bounds__(256)
void prep_kernel(const float* __restrict__ x,
                 const float* __restrict__ W1, const float* __restrict__ W2,
                 const float* __restrict__ W3,
                 __half* __restrict__ xf, __half* __restrict__ w1f,
                 __half* __restrict__ w2f, __half* __restrict__ w3f)
{
    __shared__ float s[16 * 256];     // 16 KB; weight path uses a [32][65] view
    const int b = blockIdx.x;
    const int tid = threadIdx.x;

    if (b < 2048) {
        // ---- x -> A-fragment (K=256): chunk = m_blk*(K/16)+kc, uint4 idx = chunk*32+lane
        const int mb = b & 255, ag = b >> 8;
        const float* xp = x + ((size_t)ag * ENVS + (size_t)mb * 16) * ODIM;
        #pragma unroll
        for (int i = 0; i < 16; ++i) s[tid + i * 256] = xp[tid + i * 256];
        __syncthreads();
        uint4* op = (uint4*)(xf + ((size_t)ag * ENVS + (size_t)mb * 16) * ODIM);
        #pragma unroll
        for (int j = 0; j < 2; ++j) {
            int t = tid + j * 256;
            int kc = t >> 5, ln = t & 31;
            int g = ln >> 2, tg = ln & 3;
            const float* r0 = s + g * 256 + kc * 16;
            const float* r1 = s + (g + 8) * 256 + kc * 16;
            uint4 q;
            q.x = packh2(r0[2 * tg],     r0[2 * tg + 1]);
            q.y = packh2(r1[2 * tg],     r1[2 * tg + 1]);
            q.z = packh2(r0[2 * tg + 8], r0[2 * tg + 9]);
            q.w = packh2(r1[2 * tg + 8], r1[2 * tg + 9]);
            op[kc * 32 + ln] = q;
        }
    } else {
        // ---- W [S][K][N] -> B-fragment: chunk = n_blk*(K/16)+kc, uint2 idx = chunk*32+lane
        const float* W; __half* out; int K, N, i;
        if (b < 2560)      { W = W1; out = w1f; K = ODIM; N = H1D; i = b - 2048; }
        else if (b < 4608) { W = W2; out = w2f; K = H1D;  N = H2D; i = b - 2560; }
        else               { W = W3; out = w3f; K = H2D;  N = H3D; i = b - 4608; }
        const int nb64 = N >> 6;
        const int n0 = (i % nb64) * 64;
        const int k0 = ((i / nb64) % (K >> 5)) * 32;
        const int net = i / (nb64 * (K >> 5));
        float (*t)[65] = (float(*)[65])s;
        const float* wp = W + (size_t)net * K * N;
        #pragma unroll
        for (int ii = 0; ii < 8; ++ii) {
            int o = tid + ii * 256;
            int k = o >> 6, n = o & 63;
            t[k][n] = wp[(size_t)(k0 + k) * N + n0 + n];
        }
        __syncthreads();
        uint2* op = (uint2*)(out + (size_t)net * N * K);
        const int KB16 = K >> 4;
        #pragma unroll
        for (int ii = 0; ii < 2; ++ii) {
            int tt = tid + ii * 256;
            int c = tt >> 5, ln = tt & 31;
            int nb = c >> 1, kc = c & 1;
            int g = ln >> 2, tg = ln & 3;
            uint2 q;
            q.x = packh2(t[kc * 16 + 2 * tg][nb * 8 + g],     t[kc * 16 + 2 * tg + 1][nb * 8 + g]);
            q.y = packh2(t[kc * 16 + 2 * tg + 8][nb * 8 + g], t[kc * 16 + 2 * tg + 9][nb * 8 + g]);
            int chunk = ((n0 >> 3) + nb) * KB16 + (k0 >> 4) + kc;
            op[chunk * 32 + ln] = q;
        }
    }
}

// ---------------- main GEMM: fp16 m16n8k16, k64 stages x3, reg double-buffer ----------------
// CTA 128 thr = 4 warps (2x2), CTA tile 128x128, warp tile 64x64.
// Stage 32 KB: A [8 mb][4 kc][32 ln] uint4 (16 KB) + B [16 nb][4 kc][16 ch] 16B (16 KB).
template <int K, int N, bool FINAL>
__global__ __launch_bounds__(128, 2)
void gemm_kernel(const __half* __restrict__ Af, const __half* __restrict__ Bf,
                 const float* __restrict__ bias, const void* __restrict__ seps,
                 void* __restrict__ OutV)
{
    constexpr int KC = K / 16;          // k16 chunks in global frag layout
    constexpr int NS = K / 64;          // k64 pipeline stages
    constexpr uint32_t STAGE_B = 32768;
    extern __shared__ __align__(16) float s_tile[];   // 3 stages = 96 KB

    const int tid = threadIdx.x, lane = tid & 31, warp = tid >> 5;
    const int wm = warp >> 1, wn = warp & 1;
    const int ag = blockIdx.z;
    const int sel = load_sep(seps, ag);
    const int mb0 = blockIdx.y * 8;
    const int nb0 = blockIdx.x * 16;

    const uint4* A4 = (const uint4*)(Af + (size_t)ag * ENVS * K);
    const uint4* B4 = (const uint4*)(Bf + (size_t)sel * N * K);

    // Per-thread cp.async bases. Stage advance: A +128 uint4, B +64 uint4.
    // A dst/src: thread covers kc=(tid>>5), lane=(tid&31); j = m-blk slice (compile-time offset).
    // B: nb = 2j + (tid>>6), kc = (tid&63)>>4, ib = tid&15.
    const uint4* aPtr = A4 + (size_t)mb0 * KC * 32 + (tid >> 5) * 32 + (tid & 31);
    const uint4* bPtr = B4 + (size_t)(nb0 + (tid >> 6)) * KC * 16 + ((tid & 63) >> 4) * 16 + (tid & 15);
    const uint32_t s_base = smem_u32(s_tile);
    const uint32_t dA = s_base + (uint32_t)tid * 16;
    const uint32_t dB = s_base + 16384u + (uint32_t)tid * 16;

    auto issue_stage = [&](int s, int slot) {
        uint32_t sb = (uint32_t)slot * STAGE_B;
        const uint4* ap = aPtr + (size_t)s * 128;
        const uint4* bp2 = bPtr + (size_t)s * 64;
        #pragma unroll
        for (int j = 0; j < 8; ++j)
            cp16(dA + sb + j * 2048u, ap + (size_t)j * KC * 32);
        #pragma unroll
        for (int j = 0; j < 8; ++j)
            cp16(dB + sb + j * 2048u, bp2 + (size_t)(2 * j) * KC * 16);
    };

    float acc[4][8][4];
    #pragma unroll
    for (int mi = 0; mi < 4; ++mi)
        #pragma unroll
        for (int ni = 0; ni < 8; ++ni)
            #pragma unroll
            for (int j = 0; j < 4; ++j) acc[mi][ni][j] = 0.0f;

    issue_stage(0, 0); cp_commit();
    issue_stage(1, 1); cp_commit();

    int slot_c = 0, slot_p = 2;
    #pragma unroll 1
    for (int s = 0; s < NS; ++s) {
        cp_wait<1>();
        __syncthreads();
        if (s + 2 < NS) issue_stage(s + 2, slot_p);
        cp_commit();

        const uint4* a_s = (const uint4*)(s_tile + slot_c * 8192);
        const uint2* b_s = (const uint2*)(s_tile + slot_c * 8192 + 4096);

        uint4 a[2][4];
        uint2 b[2][8];
        #pragma unroll
        for (int mi = 0; mi < 4; ++mi) a[0][mi] = a_s[(wm * 4 + mi) * 128 + lane];
        #pragma unroll
        for (int ni = 0; ni < 8; ++ni) b[0][ni] = b_s[(wn * 8 + ni) * 128 + lane];

        #pragma unroll
        for (int kc = 0; kc < 4; ++kc) {
            const int cur = kc & 1, nxt = cur ^ 1;
            if (kc < 3) {
                #pragma unroll
                for (int mi = 0; mi < 4; ++mi)
                    a[nxt][mi] = a_s[(wm * 4 + mi) * 128 + (kc + 1) * 32 + lane];
                #pragma unroll
                for (int ni = 0; ni < 8; ++ni)
                    b[nxt][ni] = b_s[(wn * 8 + ni) * 128 + (kc + 1) * 32 + lane];
            }
            #pragma unroll
            for (int mi = 0; mi < 4; ++mi)
                #pragma unroll
                for (int ni = 0; ni < 8; ++ni)
                    mma_f16(acc[mi][ni], a[cur][mi], b[cur][ni]);
        }

        if (++slot_c == 3) slot_c = 0;
        if (++slot_p == 3) slot_p = 0;
    }

    // ---------------- epilogue ----------------
    const float* bp = bias + (size_t)sel * N;
    const int g = lane >> 2, tg = lane & 3;
    const int m_blk0 = mb0 + wm * 4;
    const int n_blk0 = nb0 + wn * 8;

    if (FINAL) {
        float* ob = (float*)OutV + (size_t)ag * ENVS * N;
        #pragma unroll
        for (int mi = 0; mi < 4; ++mi) {
            const int row0 = (m_blk0 + mi) * 16 + g;
            #pragma unroll
            for (int ni = 0; ni < 8; ++ni) {
                const int nb = (n_blk0 + ni) * 8 + 2 * tg;
                const float2 bb = *(const float2*)(bp + nb);
                *(float2*)(ob + (size_t)row0 * N + nb) =
                    make_float2(acc[mi][ni][0] + bb.x, acc[mi][ni][1] + bb.y);
                *(float2*)(ob + (size_t)(row0 + 8) * N + nb) =
                    make_float2(acc[mi][ni][2] + bb.x, acc[mi][ni][3] + bb.y);
            }
        }
    } else {
        // bias + relu + fp16 round; C-frag pairs pack directly into next layer's A-frag.
        uint4* ob4 = (uint4*)((__half*)OutV + (size_t)ag * ENVS * N);
        constexpr int KCn = N / 16;
        #pragma unroll
        for (int mi = 0; mi < 4; ++mi) {
            #pragma unroll
            for (int j = 0; j < 4; ++j) {
                uint32_t h[2][2];
                #pragma unroll
                for (int e = 0; e < 2; ++e) {
                    const int ni = 2 * j + e;
                    const int nb = (n_blk0 + ni) * 8 + 2 * tg;
                    const float2 bb = *(const float2*)(bp + nb);
                    float c0 = fmaxf(acc[mi][ni][0] + bb.x, 0.0f);
                    float c1 = fmaxf(acc[mi][ni][1] + bb.y, 0.0f);
                    float c2 = fmaxf(acc[mi][ni][2] + bb.x, 0.0f);
                    float c3 = fmaxf(acc[mi][ni][3] + bb.y, 0.0f);
                    h[e][0] = packh2(c0, c1);
                    h[e][1] = packh2(c2, c3);
                }
                uint4 q;
                q.x = h[0][0]; q.y = h[0][1]; q.z = h[1][0]; q.w = h[1][1];
                const int chunk = (m_blk0 + mi) * KCn + (n_blk0 >> 1) + j;
                ob4[chunk * 32 + lane] = q;
            }
        }
    }
}

// ---------------- host ----------------
extern "C" void kernel_launch(void* const* d_in, const int* in_sizes, int n_in,
                              void* d_out, int out_size) {
    (void)in_sizes; (void)n_in; (void)out_size;
    const float* x  = (const float*)d_in[0];
    const float* W1 = (const float*)d_in[1];
    const float* b1 = (const float*)d_in[2];
    const float* W2 = (const float*)d_in[3];
    const float* b2 = (const float*)d_in[4];
    const float* W3 = (const float*)d_in[5];
    const float* b3 = (const float*)d_in[6];
    const void*  sp = d_in[7];

    __half *xf, *h1, *h2, *w1f, *w2f, *w3f;
    cudaGetSymbolAddress((void**)&xf,  g_xf);
    cudaGetSymbolAddress((void**)&h1,  g_h1);
    cudaGetSymbolAddress((void**)&h2,  g_h2);
    cudaGetSymbolAddress((void**)&w1f, g_w1f);
    cudaGetSymbolAddress((void**)&w2f, g_w2f);
    cudaGetSymbolAddress((void**)&w3f, g_w3f);

    constexpr int SMEM = 3 * 32768;   // 96 KB dynamic smem, 3 x k64 stages
    cudaFuncSetAttribute(gemm_kernel<ODIM, H1D, false>, cudaFuncAttributeMaxDynamicSharedMemorySize, SMEM);
    cudaFuncSetAttribute(gemm_kernel<H1D,  H2D, false>, cudaFuncAttributeMaxDynamicSharedMemorySize, SMEM);
    cudaFuncSetAttribute(gemm_kernel<H2D,  H3D, true >, cudaFuncAttributeMaxDynamicSharedMemorySize, SMEM);

    prep_kernel<<<5632, 256>>>(x, W1, W2, W3, xf, w1f, w2f, w3f);
    gemm_kernel<ODIM, H1D, false><<<dim3(H1D / 128, ENVS / 128, AGENTS), 128, SMEM>>>(xf, w1f, b1, sp, h1);
    gemm_kernel<H1D,  H2D, false><<<dim3(H2D / 128, ENVS / 128, AGENTS), 128, SMEM>>>(h1, w2f, b2, sp, h2);
    gemm_kernel<H2D,  H3D, true ><<<dim3(H3D / 128, ENVS / 128, AGENTS), 128, SMEM>>>(h2, w3f, b3, sp, d_out);
}